// round 6
// baseline (speedup 1.0000x reference)
#include <cuda_runtime.h>
#include <math.h>
#include <stdint.h>

// ---------------- problem constants ----------------
#define Bc      4
#define Lc      2048
#define DIMc    1024
#define DINNER  2048
#define DSTATE  16
#define DCONV   4
#define DTRANK  64
#define MROWS   (Bc*Lc)        // 8192
#define XDBL_N  96

// ---------------- scratch (device globals) ----------------
// int8 ext layout per row: [q1 (Kp) | q0 (Kp)], row length 2*Kp
__device__ __align__(128) int8_t g_xnQ  [(size_t)MROWS * 2 * 1024];
__device__ __align__(128) int8_t g_WinQ [(size_t)4096 * 2 * 1024];
__device__ __align__(128) int8_t g_ucQ  [(size_t)MROWS * 2 * 2048];
__device__ __align__(128) int8_t g_WxQ  [(size_t)128 * 2 * 2048];
__device__ __align__(128) int8_t g_dtrQ [(size_t)MROWS * 2 * 128];
__device__ __align__(128) int8_t g_WdtQ [(size_t)2048 * 2 * 128];
__device__ __align__(128) int8_t g_yQ   [(size_t)MROWS * 2 * 2048];
__device__ __align__(128) int8_t g_WoutQ[(size_t)1024 * 2 * 2048];
__device__ float g_sXn[MROWS], g_sWin[4096], g_sUc[MROWS], g_sWx[128];
__device__ float g_sDtr[MROWS], g_sWdt[2048], g_sY[MROWS], g_sWout[1024];
__device__ float g_xz  [(size_t)MROWS * 2 * DINNER];
__device__ float g_ucF [(size_t)MROWS * DINNER];
__device__ float g_xdbl[(size_t)MROWS * XDBL_N];
__device__ float g_dt  [(size_t)MROWS * DINNER];
__device__ float g_yF  [(size_t)MROWS * DINNER];

// ---------------- helpers ----------------
__device__ __forceinline__ uint32_t smem_u32(const void* p) {
    uint32_t a;
    asm("{ .reg .u64 t; cvta.to.shared.u64 t, %1; cvt.u32.u64 %0, t; }" : "=r"(a) : "l"(p));
    return a;
}
#define CP16(dst, src) asm volatile("cp.async.cg.shared.global [%0], [%1], 16;" \
    :: "r"(dst), "l"(src) : "memory")
#define CP_COMMIT()    asm volatile("cp.async.commit_group;" ::: "memory")
#define CP_WAIT(n)     asm volatile("cp.async.wait_group %0;" :: "n"(n) : "memory")

// two-digit radix-128 quantization: v = s*(128*q1 + q0) + O(s/2)
__device__ __forceinline__ void quant2(float v, float inv, int8_t& q1, int8_t& q0) {
    float q = v * inv;                         // |q| <= 16256
    int t = __float2int_rn(q * 0.0078125f);    // q/128, in [-127,127]
    int r = __float2int_rn(q - 128.f * (float)t);  // in [-64,64]
    q1 = (int8_t)t; q0 = (int8_t)r;
}

__device__ __forceinline__ float blockmax256(float v) {
    #pragma unroll
    for (int o = 16; o; o >>= 1) v = fmaxf(v, __shfl_xor_sync(0xffffffffu, v, o));
    __shared__ float s[8];
    __shared__ float r;
    int w = threadIdx.x >> 5;
    if ((threadIdx.x & 31) == 0) s[w] = v;
    __syncthreads();
    if (threadIdx.x == 0) {
        float m = s[0];
        #pragma unroll
        for (int i = 1; i < 8; i++) m = fmaxf(m, s[i]);
        r = m;
    }
    __syncthreads();
    return r;
}

// ---------------- int8 two-digit GEMM ----------------
// C[m,n] = sA[m]*sB[n]*(16384*sum(q1a*q1b) + 128*sum(q1a*q0b + q0a*q1b))
// BM=128, BN=64, BK=128 (int8), 256 threads, 4-stage cp.async ring.
#define STG_I8 24576   // A 128*128 + B 64*128

__global__ __launch_bounds__(256, 2)
void gemm_i8(const int8_t* __restrict__ A, const int8_t* __restrict__ Bw,
             float* __restrict__ C, int ldc, int Nact, int Kp,
             const float* __restrict__ sA, const float* __restrict__ sB,
             const float* __restrict__ bias,
             const float* __restrict__ resid, int ldr, int act) {
    extern __shared__ __align__(1024) unsigned char sm[];
    uint32_t sbase = smem_u32(sm);
    int tid = threadIdx.x, lane = tid & 31, wid = tid >> 5;
    int bm = blockIdx.y * 128, bn = blockIdx.x * 64;
    int wm = wid >> 1, wn = wid & 1;
    size_t lda = 2 * (size_t)Kp;

    int accH[2][4][4], accL[2][4][4];
    #pragma unroll
    for (int i = 0; i < 2; i++)
        #pragma unroll
        for (int j = 0; j < 4; j++)
            #pragma unroll
            for (int q = 0; q < 4; q++) { accH[i][j][q] = 0; accL[i][j][q] = 0; }

    const int ncc = Kp >> 7;
    const int nch = 3 * ncc;

    auto issue = [&](int stage, int c) {
        int term = (c >= ncc) + (c >= 2 * ncc);
        int cc = c - term * ncc;
        int aoff = ((term == 2) ? Kp : 0) + cc * 128;
        int boff = ((term == 1) ? Kp : 0) + cc * 128;
        uint32_t sAm = sbase + stage * STG_I8;
        uint32_t sBm = sAm + 16384;
        #pragma unroll
        for (int it = 0; it < 4; it++) {
            int idx = tid + it * 256;
            int r = idx >> 3, u = idx & 7;
            CP16(sAm + r * 128 + ((u ^ (r & 7)) << 4),
                 __cvta_generic_to_global(A + (size_t)(bm + r) * lda + aoff + u * 16));
        }
        #pragma unroll
        for (int it = 0; it < 2; it++) {
            int idx = tid + it * 256;
            int r = idx >> 3, u = idx & 7;
            CP16(sBm + r * 128 + ((u ^ (r & 7)) << 4),
                 __cvta_generic_to_global(Bw + (size_t)(bn + r) * lda + boff + u * 16));
        }
        CP_COMMIT();
    };

    issue(0, 0);
    if (nch > 1) issue(1, 1);
    if (nch > 2) issue(2, 2);

    for (int c = 0; c < nch; c++) {
        int stage = c & 3;
        if (c + 3 < nch) { issue((c + 3) & 3, c + 3); CP_WAIT(3); }
        else if (c + 2 < nch) CP_WAIT(2);
        else if (c + 1 < nch) CP_WAIT(1);
        else CP_WAIT(0);
        __syncthreads();

        int term = (c >= ncc) + (c >= 2 * ncc);
        uint32_t sAm = sbase + stage * STG_I8;
        uint32_t sBm = sAm + 16384;
        #pragma unroll
        for (int ks = 0; ks < 4; ks++) {
            uint32_t a[2][4], b[4][2];
            #pragma unroll
            for (int i = 0; i < 2; i++) {
                int r = wm * 32 + i * 16 + (lane & 15);
                int u = ks * 2 + (lane >> 4);
                uint32_t addr = sAm + r * 128 + ((u ^ (r & 7)) << 4);
                asm volatile("ldmatrix.sync.aligned.m8n8.x4.shared.b16 {%0,%1,%2,%3}, [%4];"
                    : "=r"(a[i][0]), "=r"(a[i][1]), "=r"(a[i][2]), "=r"(a[i][3]) : "r"(addr));
            }
            #pragma unroll
            for (int jj = 0; jj < 2; jj++) {
                int r = wn * 32 + jj * 16 + ((lane >> 4) << 3) + (lane & 7);
                int u = ks * 2 + ((lane >> 3) & 1);
                uint32_t addr = sBm + r * 128 + ((u ^ (r & 7)) << 4);
                asm volatile("ldmatrix.sync.aligned.m8n8.x4.shared.b16 {%0,%1,%2,%3}, [%4];"
                    : "=r"(b[jj*2][0]), "=r"(b[jj*2][1]), "=r"(b[jj*2+1][0]), "=r"(b[jj*2+1][1])
                    : "r"(addr));
            }
            auto mmas = [&](int (&acc)[2][4][4]) {
                #pragma unroll
                for (int i = 0; i < 2; i++)
                    #pragma unroll
                    for (int j = 0; j < 4; j++)
                        asm volatile(
                            "mma.sync.aligned.m16n8k32.row.col.s32.s8.s8.s32 "
                            "{%0,%1,%2,%3}, {%4,%5,%6,%7}, {%8,%9}, {%0,%1,%2,%3};"
                            : "+r"(acc[i][j][0]), "+r"(acc[i][j][1]),
                              "+r"(acc[i][j][2]), "+r"(acc[i][j][3])
                            : "r"(a[i][0]), "r"(a[i][1]), "r"(a[i][2]), "r"(a[i][3]),
                              "r"(b[j][0]), "r"(b[j][1]));
            };
            if (term == 0) mmas(accH); else mmas(accL);
        }
        __syncthreads();
    }

    // ---- epilogue ----
    #pragma unroll
    for (int i = 0; i < 2; i++) {
        int r0 = bm + wm * 32 + i * 16 + (lane >> 2);
        float sa0 = sA[r0], sa1 = sA[r0 + 8];
        #pragma unroll
        for (int j = 0; j < 4; j++) {
            int n0 = bn + wn * 32 + j * 8 + 2 * (lane & 3);
            float sb0 = sB[n0], sb1 = sB[n0 + 1];
            #pragma unroll
            for (int h = 0; h < 2; h++) {
                int r = r0 + h * 8;
                float sa = h ? sa1 : sa0;
                float v0 = sa * sb0 * (16384.f * (float)accH[i][j][h*2+0] + 128.f * (float)accL[i][j][h*2+0]);
                float v1 = sa * sb1 * (16384.f * (float)accH[i][j][h*2+1] + 128.f * (float)accL[i][j][h*2+1]);
                if (bias) { v0 += bias[n0]; v1 += bias[n0 + 1]; }
                if (act) {
                    v0 = (v0 > 20.f) ? v0 : log1pf(expf(v0));
                    v1 = (v1 > 20.f) ? v1 : log1pf(expf(v1));
                }
                if (resid) {
                    v0 += resid[(size_t)r * ldr + n0];
                    v1 += resid[(size_t)r * ldr + n0 + 1];
                }
                if (n0 + 1 < Nact) {
                    *(float2*)(C + (size_t)r * ldc + n0) = make_float2(v0, v1);
                } else if (n0 < Nact) {
                    C[(size_t)r * ldc + n0] = v0;
                }
            }
        }
    }
}

// ---------------- generic row quantizer (weights / dtr / y) ----------------
__global__ __launch_bounds__(256)
void quant_rows(const float* __restrict__ src, int ldsrc, int Kact, int Kp, int Rin,
                int8_t* __restrict__ out, float* __restrict__ sOut) {
    int r = blockIdx.x;
    int tid = threadIdx.x;
    __shared__ float buf[2048];
    float mx = 0.f;
    if (r < Rin)
        for (int k = tid; k < Kact; k += 256) {
            float v = src[(size_t)r * ldsrc + k];
            buf[k] = v;
            mx = fmaxf(mx, fabsf(v));
        }
    mx = blockmax256(mx);
    float mg = fmaxf(mx, 1e-20f);
    float inv = 16256.f / mg;
    if (tid == 0) sOut[r] = mg / 16256.f;
    int8_t* o = out + (size_t)r * 2 * Kp;
    for (int k = tid; k < Kp; k += 256) {
        int8_t h = 0, l = 0;
        if (r < Rin && k < Kact) quant2(buf[k], inv, h, l);
        o[k] = h;
        o[Kp + k] = l;
    }
}

// ---------------- LayerNorm -> quantized row ----------------
__global__ __launch_bounds__(256)
void ln_q(const float* __restrict__ x, const float* __restrict__ g,
          const float* __restrict__ b) {
    int row = blockIdx.x, tid = threadIdx.x;
    const float* xr = x + (size_t)row * DIMc;
    __shared__ float buf[DIMc];
    float sum = 0.f, sq = 0.f;
    for (int i = tid; i < DIMc; i += 256) {
        float v = xr[i];
        sum += v; sq += v * v;
    }
    #pragma unroll
    for (int o = 16; o; o >>= 1) {
        sum += __shfl_xor_sync(0xffffffffu, sum, o);
        sq  += __shfl_xor_sync(0xffffffffu, sq, o);
    }
    __shared__ float s1[8], s2[8], red[2];
    int w = tid >> 5, l = tid & 31;
    if (l == 0) { s1[w] = sum; s2[w] = sq; }
    __syncthreads();
    if (tid == 0) {
        float a = 0.f, c = 0.f;
        #pragma unroll
        for (int i = 0; i < 8; i++) { a += s1[i]; c += s2[i]; }
        float mu = a / DIMc;
        red[0] = mu;
        red[1] = c / DIMc - mu * mu;
    }
    __syncthreads();
    float mu = red[0];
    float inv = rsqrtf(red[1] + 1e-5f);
    float mx = 0.f;
    for (int i = tid; i < DIMc; i += 256) {
        float v = (xr[i] - mu) * inv * g[i] + b[i];
        buf[i] = v;
        mx = fmaxf(mx, fabsf(v));
    }
    mx = blockmax256(mx);
    float mg = fmaxf(mx, 1e-20f);
    float qinv = 16256.f / mg;
    if (tid == 0) g_sXn[row] = mg / 16256.f;
    int8_t* o = g_xnQ + (size_t)row * 2 * DIMc;
    for (int i = tid; i < DIMc; i += 256) {
        int8_t h, lo;
        quant2(buf[i], qinv, h, lo);
        o[i] = h;
        o[DIMc + i] = lo;
    }
}

// ---------------- depthwise conv + SiLU -> fp32 + quantized row ----------------
__global__ __launch_bounds__(256)
void conv_q(const float* __restrict__ convw, const float* __restrict__ convb) {
    int m = blockIdx.x, tid = threadIdx.x;
    int l = m & (Lc - 1);
    __shared__ float buf[DINNER];
    float mx = 0.f;
    for (int d = tid; d < DINNER; d += 256) {
        float acc = convb[d];
        #pragma unroll
        for (int k = 0; k < DCONV; k++) {
            int ll = l - (DCONV - 1) + k;
            if (ll >= 0)
                acc = fmaf(g_xz[(size_t)(m - (DCONV - 1) + k) * (2 * DINNER) + d],
                           convw[d * DCONV + k], acc);
        }
        acc = acc / (1.f + expf(-acc));
        g_ucF[(size_t)m * DINNER + d] = acc;
        buf[d] = acc;
        mx = fmaxf(mx, fabsf(acc));
    }
    mx = blockmax256(mx);
    float mg = fmaxf(mx, 1e-20f);
    float qinv = 16256.f / mg;
    if (tid == 0) g_sUc[m] = mg / 16256.f;
    int8_t* o = g_ucQ + (size_t)m * 2 * DINNER;
    for (int d = tid; d < DINNER; d += 256) {
        int8_t h, lo;
        quant2(buf[d], qinv, h, lo);
        o[d] = h;
        o[DINNER + d] = lo;
    }
}

// ---------------- selective scan + gate -> yF fp32 ----------------
__global__ __launch_bounds__(256)
void scan_kernel(const float* __restrict__ A_log, const float* __restrict__ Dp) {
    int t = blockIdx.x * 256 + threadIdx.x;
    int n = t & 15;
    int d = (t >> 4) & (DINNER - 1);
    int b = t >> 15;
    float A  = -expf(A_log[d * DSTATE + n]);
    float Dd = Dp[d];
    float h  = 0.f;
    size_t base = (size_t)b * Lc;
    for (int l = 0; l < Lc; l++) {
        size_t m = base + l;
        float dt = g_dt[m * DINNER + d];
        float u  = g_ucF[m * DINNER + d];
        float Bn = g_xdbl[m * XDBL_N + DTRANK + n];
        float Cn = g_xdbl[m * XDBL_N + DTRANK + DSTATE + n];
        float dA = expf(dt * A);
        h = fmaf(dA, h, dt * u * Bn);
        float p = h * Cn;
        p += __shfl_xor_sync(0xffffffffu, p, 8);
        p += __shfl_xor_sync(0xffffffffu, p, 4);
        p += __shfl_xor_sync(0xffffffffu, p, 2);
        p += __shfl_xor_sync(0xffffffffu, p, 1);
        if (n == 0) {
            float z = g_xz[m * (2 * DINNER) + DINNER + d];
            float y = (p + u * Dd) * (z / (1.f + expf(-z)));
            g_yF[m * DINNER + d] = y;
        }
    }
}

// ---------------- launch ----------------
extern "C" void kernel_launch(void* const* d_in, const int* in_sizes, int n_in,
                              void* d_out, int out_size) {
    const float* x      = (const float*)d_in[0];
    const float* ln_g   = (const float*)d_in[1];
    const float* ln_b   = (const float*)d_in[2];
    const float* W_in   = (const float*)d_in[3];
    const float* conv_w = (const float*)d_in[4];
    const float* conv_b = (const float*)d_in[5];
    const float* W_x    = (const float*)d_in[6];
    const float* W_dt   = (const float*)d_in[7];
    const float* b_dt   = (const float*)d_in[8];
    const float* A_log  = (const float*)d_in[9];
    const float* Dvec   = (const float*)d_in[10];
    const float* W_out  = (const float*)d_in[11];
    float* out = (float*)d_out;

    int8_t *xnQ, *WinQ, *ucQ, *WxQ, *dtrQ, *WdtQ, *yQ, *WoutQ;
    float *sXn, *sWin, *sUc, *sWx, *sDtr, *sWdt, *sY, *sWout;
    float *xz, *xdbl, *dt, *yF;
    cudaGetSymbolAddress((void**)&xnQ,   g_xnQ);
    cudaGetSymbolAddress((void**)&WinQ,  g_WinQ);
    cudaGetSymbolAddress((void**)&ucQ,   g_ucQ);
    cudaGetSymbolAddress((void**)&WxQ,   g_WxQ);
    cudaGetSymbolAddress((void**)&dtrQ,  g_dtrQ);
    cudaGetSymbolAddress((void**)&WdtQ,  g_WdtQ);
    cudaGetSymbolAddress((void**)&yQ,    g_yQ);
    cudaGetSymbolAddress((void**)&WoutQ, g_WoutQ);
    cudaGetSymbolAddress((void**)&sXn,   g_sXn);
    cudaGetSymbolAddress((void**)&sWin,  g_sWin);
    cudaGetSymbolAddress((void**)&sUc,   g_sUc);
    cudaGetSymbolAddress((void**)&sWx,   g_sWx);
    cudaGetSymbolAddress((void**)&sDtr,  g_sDtr);
    cudaGetSymbolAddress((void**)&sWdt,  g_sWdt);
    cudaGetSymbolAddress((void**)&sY,    g_sY);
    cudaGetSymbolAddress((void**)&sWout, g_sWout);
    cudaGetSymbolAddress((void**)&xz,    g_xz);
    cudaGetSymbolAddress((void**)&xdbl,  g_xdbl);
    cudaGetSymbolAddress((void**)&dt,    g_dt);
    cudaGetSymbolAddress((void**)&yF,    g_yF);

    static int smem_set = 0;
    if (!smem_set) {
        cudaFuncSetAttribute(gemm_i8, cudaFuncAttributeMaxDynamicSharedMemorySize, 4 * STG_I8);
        smem_set = 1;
    }
    const int SMB = 4 * STG_I8;   // 98304

    // weight quantization
    quant_rows<<<4096, 256>>>(W_in,  DIMc,   DIMc,   DIMc,   4096,  WinQ,  sWin);
    quant_rows<<<128,  256>>>(W_x,   DINNER, DINNER, DINNER, XDBL_N, WxQ,  sWx);
    quant_rows<<<2048, 256>>>(W_dt,  DTRANK, DTRANK, 128,    DINNER, WdtQ, sWdt);
    quant_rows<<<1024, 256>>>(W_out, DINNER, DINNER, DINNER, DIMc,  WoutQ, sWout);

    // LN + quant
    ln_q<<<MROWS, 256>>>(x, ln_g, ln_b);

    // GEMM1: xz = xn @ W_in^T   (8192 x 4096, Kp=1024)
    gemm_i8<<<dim3(4096 / 64, MROWS / 128), 256, SMB>>>(
        xnQ, WinQ, xz, 2 * DINNER, 2 * DINNER, DIMc, sXn, sWin,
        nullptr, nullptr, 0, 0);

    // conv + SiLU + quant
    conv_q<<<MROWS, 256>>>(conv_w, conv_b);

    // GEMM2: x_dbl = uc @ W_x^T  (8192 x 96 pad 128, Kp=2048)
    gemm_i8<<<dim3(2, MROWS / 128), 256, SMB>>>(
        ucQ, WxQ, xdbl, XDBL_N, XDBL_N, DINNER, sUc, sWx,
        nullptr, nullptr, 0, 0);

    // dt_r quant (first 64 cols of x_dbl, Kp padded to 128)
    quant_rows<<<MROWS, 256>>>(xdbl, XDBL_N, DTRANK, 128, MROWS, dtrQ, sDtr);

    // GEMM3: dt = softplus(dt_r @ W_dt^T + b_dt)  (8192 x 2048, Kp=128)
    gemm_i8<<<dim3(DINNER / 64, MROWS / 128), 256, SMB>>>(
        dtrQ, WdtQ, dt, DINNER, DINNER, 128, sDtr, sWdt,
        b_dt, nullptr, 0, 1);

    // scan + gate -> yF
    scan_kernel<<<(Bc * DINNER * DSTATE) / 256, 256>>>(A_log, Dvec);

    // y quant
    quant_rows<<<MROWS, 256>>>(yF, DINNER, DINNER, DINNER, MROWS, yQ, sY);

    // GEMM4: out = x + y @ W_out^T  (8192 x 1024, Kp=2048)
    gemm_i8<<<dim3(DIMc / 64, MROWS / 128), 256, SMB>>>(
        yQ, WoutQ, out, DIMc, DIMc, DINNER, sY, sWout,
        nullptr, x, DIMc, 0);
}

// round 7
// speedup vs baseline: 1.5726x; 1.5726x over previous
#include <cuda_runtime.h>
#include <cuda_fp16.h>
#include <math.h>
#include <stdint.h>

// ---------------- problem constants ----------------
#define Bc      4
#define Lc      2048
#define DIMc    1024
#define DINNER  2048
#define DSTATE  16
#define DCONV   4
#define DTRANK  64
#define MROWS   (Bc*Lc)        // 8192
#define XDBL_N  96

// ---------------- scratch (device globals) ----------------
// activations: single fp16 digit. weights: [hi(K) | lo(K)] fp16 two-digit rows.
__device__ __align__(128) __half g_xnH  [(size_t)MROWS * 1024];
__device__ __align__(128) __half g_WinH [(size_t)4096 * 2 * 1024];
__device__ __align__(128) __half g_ucH  [(size_t)MROWS * 2048];
__device__ __align__(128) __half g_WxH  [(size_t)128 * 2 * 2048];
__device__ __align__(128) __half g_dtrH [(size_t)MROWS * 128];
__device__ __align__(128) __half g_WdtH [(size_t)2048 * 2 * 128];
__device__ __align__(128) __half g_yH   [(size_t)MROWS * 2048];
__device__ __align__(128) __half g_WoutH[(size_t)1024 * 2 * 2048];
__device__ float g_xz  [(size_t)MROWS * 2 * DINNER];
__device__ float g_ucF [(size_t)MROWS * DINNER];
__device__ float g_xdbl[(size_t)MROWS * XDBL_N];
__device__ float g_dt  [(size_t)MROWS * DINNER];

// ---------------- helpers ----------------
__device__ __forceinline__ uint32_t smem_u32(const void* p) {
    uint32_t a;
    asm("{ .reg .u64 t; cvta.to.shared.u64 t, %1; cvt.u32.u64 %0, t; }" : "=r"(a) : "l"(p));
    return a;
}
#define CP16(dst, src) asm volatile("cp.async.cg.shared.global [%0], [%1], 16;" \
    :: "r"(dst), "l"(src) : "memory")
#define CP_COMMIT()    asm volatile("cp.async.commit_group;" ::: "memory")
#define CP_WAIT(n)     asm volatile("cp.async.wait_group %0;" :: "n"(n) : "memory")

__device__ __forceinline__ void split_h2(float v, __half& h, __half& l) {
    h = __float2half(v);
    l = __float2half(v - __half2float(h));
}

// ---------------- fp16 2-term GEMM ----------------
// C[m,n] = sum_k Ah[m,k]*(Bh[n,k] + Bl[n,k]);  A 1-digit fp16 (lda=Kh),
// B 2-digit fp16 [hi|lo] (ldb=2*Kh).  BM x 128 tile, BK=64, 3-stage cp.async.
template<int BM>
__global__ __launch_bounds__(256, 2)
void gemm_h2(const __half* __restrict__ A,
             const __half* __restrict__ Bw,
             float* __restrict__ C, int ldc, int Nact, int Kh,
             const float* __restrict__ bias,
             const float* __restrict__ resid, int ldr, int act) {
    constexpr int ABYTES = BM * 128;          // BM rows x 64 fp16
    constexpr int BBYTES = 128 * 128;
    constexpr int STG    = ABYTES + BBYTES;
    constexpr int WMC    = BM / 32;
    constexpr int WNC    = 8 / WMC;
    constexpr int WTN    = 128 / WNC;
    constexpr int BJ     = WTN / 8;

    extern __shared__ __align__(1024) unsigned char sm[];
    uint32_t sbase = smem_u32(sm);
    int tid = threadIdx.x, lane = tid & 31, wid = tid >> 5;
    int bm = blockIdx.y * BM, bn = blockIdx.x * 128;
    int wm = wid % WMC, wn = wid / WMC;
    size_t lda = (size_t)Kh;
    size_t ldb = 2 * (size_t)Kh;

    float acc[2][BJ][4];
    #pragma unroll
    for (int i = 0; i < 2; i++)
        #pragma unroll
        for (int j = 0; j < BJ; j++)
            #pragma unroll
            for (int q = 0; q < 4; q++) acc[i][j][q] = 0.f;

    const int ncc = Kh >> 6;
    const int nch = 2 * ncc;     // term 0: B-hi, term 1: B-lo

    auto issue_load = [&](int stage, int c) {
        int term = (c >= ncc);
        int cc   = c - term * ncc;
        int aoff = cc * 64;
        int boff = term * Kh + cc * 64;
        uint32_t sA = sbase + stage * STG;
        uint32_t sB = sA + ABYTES;
        #pragma unroll
        for (int it = 0; it < BM / 32; it++) {
            int idx = tid + it * 256;
            int r = idx >> 3, u = idx & 7;
            CP16(sA + r * 128 + ((u ^ (r & 7)) << 4),
                 __cvta_generic_to_global(A + (size_t)(bm + r) * lda + aoff + u * 8));
        }
        #pragma unroll
        for (int it = 0; it < 4; it++) {
            int idx = tid + it * 256;
            int r = idx >> 3, u = idx & 7;
            CP16(sB + r * 128 + ((u ^ (r & 7)) << 4),
                 __cvta_generic_to_global(Bw + (size_t)(bn + r) * ldb + boff + u * 8));
        }
        CP_COMMIT();
    };

    issue_load(0, 0);
    if (nch > 1) issue_load(1, 1);

    for (int c = 0; c < nch; c++) {
        int stage = c % 3;
        if (c + 2 < nch) { issue_load((c + 2) % 3, c + 2); CP_WAIT(2); }
        else if (c + 1 < nch) CP_WAIT(1);
        else CP_WAIT(0);
        __syncthreads();

        uint32_t sA = sbase + stage * STG;
        uint32_t sB = sA + ABYTES;
        #pragma unroll
        for (int ks = 0; ks < 4; ks++) {
            uint32_t a[2][4], b[BJ][2];
            #pragma unroll
            for (int i = 0; i < 2; i++) {
                int r = wm * 32 + i * 16 + (lane & 15);
                int u = ks * 2 + (lane >> 4);
                uint32_t addr = sA + r * 128 + ((u ^ (r & 7)) << 4);
                asm volatile("ldmatrix.sync.aligned.m8n8.x4.shared.b16 {%0,%1,%2,%3}, [%4];"
                    : "=r"(a[i][0]), "=r"(a[i][1]), "=r"(a[i][2]), "=r"(a[i][3]) : "r"(addr));
            }
            #pragma unroll
            for (int jj = 0; jj < BJ / 2; jj++) {
                int r = wn * WTN + jj * 16 + ((lane >> 4) << 3) + (lane & 7);
                int u = ks * 2 + ((lane >> 3) & 1);
                uint32_t addr = sB + r * 128 + ((u ^ (r & 7)) << 4);
                asm volatile("ldmatrix.sync.aligned.m8n8.x4.shared.b16 {%0,%1,%2,%3}, [%4];"
                    : "=r"(b[jj*2][0]), "=r"(b[jj*2][1]), "=r"(b[jj*2+1][0]), "=r"(b[jj*2+1][1])
                    : "r"(addr));
            }
            #pragma unroll
            for (int i = 0; i < 2; i++)
                #pragma unroll
                for (int j = 0; j < BJ; j++)
                    asm volatile(
                        "mma.sync.aligned.m16n8k16.row.col.f32.f16.f16.f32 "
                        "{%0,%1,%2,%3}, {%4,%5,%6,%7}, {%8,%9}, {%0,%1,%2,%3};"
                        : "+f"(acc[i][j][0]), "+f"(acc[i][j][1]),
                          "+f"(acc[i][j][2]), "+f"(acc[i][j][3])
                        : "r"(a[i][0]), "r"(a[i][1]), "r"(a[i][2]), "r"(a[i][3]),
                          "r"(b[j][0]), "r"(b[j][1]));
        }
        __syncthreads();
    }

    // ---- epilogue ----
    #pragma unroll
    for (int i = 0; i < 2; i++) {
        int r0 = bm + wm * 32 + i * 16 + (lane >> 2);
        #pragma unroll
        for (int j = 0; j < BJ; j++) {
            int n0 = bn + wn * WTN + j * 8 + 2 * (lane & 3);
            #pragma unroll
            for (int h = 0; h < 2; h++) {
                int r = r0 + h * 8;
                float v0 = acc[i][j][h * 2 + 0];
                float v1 = acc[i][j][h * 2 + 1];
                if (bias) { v0 += bias[n0]; v1 += bias[n0 + 1]; }
                if (act) {
                    v0 = (v0 > 20.f) ? v0 : log1pf(expf(v0));
                    v1 = (v1 > 20.f) ? v1 : log1pf(expf(v1));
                }
                if (resid) {
                    v0 += resid[(size_t)r * ldr + n0];
                    v1 += resid[(size_t)r * ldr + n0 + 1];
                }
                if (n0 + 1 < Nact) {
                    *(float2*)(C + (size_t)r * ldc + n0) = make_float2(v0, v1);
                } else if (n0 < Nact) {
                    C[(size_t)r * ldc + n0] = v0;
                }
            }
        }
    }
}

// ---------------- weight -> fp16 two-digit (row/col padding) ----------------
__global__ __launch_bounds__(256)
void wext2_kernel(const float* __restrict__ W, __half* __restrict__ out,
                  int Rin, int Kact, int Kp, int total) {
    int idx = blockIdx.x * 256 + threadIdx.x;
    if (idx >= total) return;
    int r = idx / Kp, k = idx - r * Kp;
    float v = (r < Rin && k < Kact) ? W[(size_t)r * Kact + k] : 0.f;
    __half h, l;
    split_h2(v, h, l);
    out[(size_t)r * 2 * Kp + k]      = h;
    out[(size_t)r * 2 * Kp + Kp + k] = l;
}

// ---------------- LayerNorm -> fp16 ----------------
__global__ __launch_bounds__(256)
void ln_h(const float* __restrict__ x, const float* __restrict__ g,
          const float* __restrict__ b) {
    int row = blockIdx.x, tid = threadIdx.x;
    const float* xr = x + (size_t)row * DIMc;
    float sum = 0.f, sq = 0.f;
    for (int i = tid; i < DIMc; i += 256) {
        float v = xr[i];
        sum += v; sq += v * v;
    }
    #pragma unroll
    for (int o = 16; o; o >>= 1) {
        sum += __shfl_xor_sync(0xffffffffu, sum, o);
        sq  += __shfl_xor_sync(0xffffffffu, sq, o);
    }
    __shared__ float s1[8], s2[8], red[2];
    int w = tid >> 5, l = tid & 31;
    if (l == 0) { s1[w] = sum; s2[w] = sq; }
    __syncthreads();
    if (tid == 0) {
        float a = 0.f, c = 0.f;
        #pragma unroll
        for (int i = 0; i < 8; i++) { a += s1[i]; c += s2[i]; }
        float mu = a / DIMc;
        red[0] = mu;
        red[1] = c / DIMc - mu * mu;
    }
    __syncthreads();
    float mu = red[0];
    float inv = rsqrtf(red[1] + 1e-5f);
    __half* o = g_xnH + (size_t)row * DIMc;
    for (int i = tid; i < DIMc; i += 256)
        o[i] = __float2half((xr[i] - mu) * inv * g[i] + b[i]);
}

// ---------------- depthwise conv + SiLU -> fp32 + fp16 ----------------
__global__ __launch_bounds__(256)
void conv_h(const float* __restrict__ convw, const float* __restrict__ convb) {
    int idx = blockIdx.x * 256 + threadIdx.x;
    if (idx >= MROWS * DINNER) return;
    int d = idx & (DINNER - 1);
    int m = idx >> 11;
    int l = m & (Lc - 1);
    float acc = convb[d];
    #pragma unroll
    for (int k = 0; k < DCONV; k++) {
        int ll = l - (DCONV - 1) + k;
        if (ll >= 0)
            acc = fmaf(g_xz[(size_t)(m - (DCONV - 1) + k) * (2 * DINNER) + d],
                       convw[d * DCONV + k], acc);
    }
    acc = acc / (1.f + expf(-acc));
    g_ucF[idx] = acc;
    g_ucH[idx] = __float2half(acc);
}

// ---------------- dt_r slice -> fp16 (pad 64->128) ----------------
__global__ __launch_bounds__(256)
void dtr_h() {
    int idx = blockIdx.x * 256 + threadIdx.x;
    if (idx >= MROWS * 128) return;
    int m = idx >> 7, k = idx & 127;
    float v = (k < DTRANK) ? g_xdbl[(size_t)m * XDBL_N + k] : 0.f;
    g_dtrH[idx] = __float2half(v);
}

// ---------------- selective scan + gate -> fp16 y ----------------
__global__ __launch_bounds__(256)
void scan_kernel(const float* __restrict__ A_log, const float* __restrict__ Dp) {
    int t = blockIdx.x * 256 + threadIdx.x;
    int n = t & 15;
    int d = (t >> 4) & (DINNER - 1);
    int b = t >> 15;
    float A  = -expf(A_log[d * DSTATE + n]);
    float Dd = Dp[d];
    float h  = 0.f;
    size_t base = (size_t)b * Lc;
    for (int l = 0; l < Lc; l++) {
        size_t m = base + l;
        float dt = g_dt[m * DINNER + d];
        float u  = g_ucF[m * DINNER + d];
        float Bn = g_xdbl[m * XDBL_N + DTRANK + n];
        float Cn = g_xdbl[m * XDBL_N + DTRANK + DSTATE + n];
        float dA = expf(dt * A);
        h = fmaf(dA, h, dt * u * Bn);
        float p = h * Cn;
        p += __shfl_xor_sync(0xffffffffu, p, 8);
        p += __shfl_xor_sync(0xffffffffu, p, 4);
        p += __shfl_xor_sync(0xffffffffu, p, 2);
        p += __shfl_xor_sync(0xffffffffu, p, 1);
        if (n == 0) {
            float z = g_xz[m * (2 * DINNER) + DINNER + d];
            float y = (p + u * Dd) * (z / (1.f + expf(-z)));
            g_yH[m * DINNER + d] = __float2half(y);
        }
    }
}

// ---------------- launch ----------------
extern "C" void kernel_launch(void* const* d_in, const int* in_sizes, int n_in,
                              void* d_out, int out_size) {
    const float* x      = (const float*)d_in[0];
    const float* ln_g   = (const float*)d_in[1];
    const float* ln_b   = (const float*)d_in[2];
    const float* W_in   = (const float*)d_in[3];
    const float* conv_w = (const float*)d_in[4];
    const float* conv_b = (const float*)d_in[5];
    const float* W_x    = (const float*)d_in[6];
    const float* W_dt   = (const float*)d_in[7];
    const float* b_dt   = (const float*)d_in[8];
    const float* A_log  = (const float*)d_in[9];
    const float* Dvec   = (const float*)d_in[10];
    const float* W_out  = (const float*)d_in[11];
    float* out = (float*)d_out;

    __half *xnH, *WinH, *ucH, *WxH, *dtrH, *WdtH, *yH, *WoutH;
    float *xz, *xdbl, *dt;
    cudaGetSymbolAddress((void**)&xnH,   g_xnH);
    cudaGetSymbolAddress((void**)&WinH,  g_WinH);
    cudaGetSymbolAddress((void**)&ucH,   g_ucH);
    cudaGetSymbolAddress((void**)&WxH,   g_WxH);
    cudaGetSymbolAddress((void**)&dtrH,  g_dtrH);
    cudaGetSymbolAddress((void**)&WdtH,  g_WdtH);
    cudaGetSymbolAddress((void**)&yH,    g_yH);
    cudaGetSymbolAddress((void**)&WoutH, g_WoutH);
    cudaGetSymbolAddress((void**)&xz,    g_xz);
    cudaGetSymbolAddress((void**)&xdbl,  g_xdbl);
    cudaGetSymbolAddress((void**)&dt,    g_dt);

    static int smem_set = 0;
    if (!smem_set) {
        cudaFuncSetAttribute(gemm_h2<128>, cudaFuncAttributeMaxDynamicSharedMemorySize, 3 * (128 * 128 + 128 * 128));
        cudaFuncSetAttribute(gemm_h2<64>,  cudaFuncAttributeMaxDynamicSharedMemorySize, 3 * (64 * 128 + 128 * 128));
        smem_set = 1;
    }
    const int SM128 = 3 * (128 * 128 + 128 * 128);   // 98304
    const int SM64  = 3 * (64 * 128 + 128 * 128);    // 73728

    // weight conversions (2-digit fp16)
    wext2_kernel<<<(4096 * 1024 + 255) / 256, 256>>>(W_in,  WinH,  4096,   DIMc,   DIMc,   4096 * 1024);
    wext2_kernel<<<(128 * 2048 + 255) / 256, 256>>>(W_x,   WxH,   XDBL_N, DINNER, DINNER, 128 * 2048);
    wext2_kernel<<<(2048 * 128 + 255) / 256, 256>>>(W_dt,  WdtH,  DINNER, DTRANK, 128,    2048 * 128);
    wext2_kernel<<<(1024 * 2048 + 255) / 256, 256>>>(W_out, WoutH, DIMc,   DINNER, DINNER, 1024 * 2048);

    // LN -> fp16
    ln_h<<<MROWS, 256>>>(x, ln_g, ln_b);

    // GEMM1: xz = xn @ W_in^T   (8192 x 4096, Kh=1024)
    gemm_h2<128><<<dim3(4096 / 128, MROWS / 128), 256, SM128>>>(
        xnH, WinH, xz, 2 * DINNER, 2 * DINNER, DIMc, nullptr, nullptr, 0, 0);

    // conv + SiLU
    conv_h<<<(MROWS * DINNER) / 256, 256>>>(conv_w, conv_b);

    // GEMM2: x_dbl = uc @ W_x^T  (8192 x 96 pad 128, Kh=2048), BM=64 for occupancy
    gemm_h2<64><<<dim3(1, MROWS / 64), 256, SM64>>>(
        ucH, WxH, xdbl, XDBL_N, XDBL_N, DINNER, nullptr, nullptr, 0, 0);

    // dt_r -> fp16
    dtr_h<<<(MROWS * 128) / 256, 256>>>();

    // GEMM3: dt = softplus(dt_r @ W_dt^T + b_dt)  (8192 x 2048, Kh=128)
    gemm_h2<128><<<dim3(DINNER / 128, MROWS / 128), 256, SM128>>>(
        dtrH, WdtH, dt, DINNER, DINNER, 128, b_dt, nullptr, 0, 1);

    // scan + gate -> yH
    scan_kernel<<<(Bc * DINNER * DSTATE) / 256, 256>>>(A_log, Dvec);

    // GEMM4: out = x + y @ W_out^T  (8192 x 1024, Kh=2048)
    gemm_h2<128><<<dim3(DIMc / 128, MROWS / 128), 256, SM128>>>(
        yH, WoutH, out, DIMc, DIMc, DINNER, nullptr, x, DIMc, 0);
}

// round 8
// speedup vs baseline: 2.6668x; 1.6958x over previous
#include <cuda_runtime.h>
#include <cuda_fp16.h>
#include <math.h>
#include <stdint.h>

// ---------------- problem constants ----------------
#define Bc      4
#define Lc      2048
#define DIMc    1024
#define DINNER  2048
#define DSTATE  16
#define DCONV   4
#define DTRANK  64
#define MROWS   (Bc*Lc)        // 8192
#define XDBL_N  96
#define CH      8              // scan chunks
#define CL      (Lc/CH)        // 256 tokens per chunk

// ---------------- scratch (device globals) ----------------
__device__ __align__(128) __half g_xnH  [(size_t)MROWS * 1024];
__device__ __align__(128) __half g_WinH [(size_t)4096 * 1024];
__device__ __align__(128) __half g_xzH  [(size_t)MROWS * 4096];   // u|z fp16
__device__ __align__(128) __half g_ucH  [(size_t)MROWS * 2048];
__device__ __align__(128) __half g_WxH  [(size_t)128 * 2048];
__device__ float                 g_xdbl [(size_t)MROWS * XDBL_N]; // B,C,dt_r fp32
__device__ __align__(128) __half g_dtrH [(size_t)MROWS * 128];
__device__ __align__(128) __half g_WdtH [(size_t)2048 * 128];
__device__ __align__(128) __half g_dtH  [(size_t)MROWS * 2048];
__device__ __align__(128) __half g_yH   [(size_t)MROWS * 2048];
__device__ __align__(128) __half g_WoutH[(size_t)1024 * 2048];
// chunked-scan state: [Bc][CH][DINNER][DSTATE]
__device__ float g_aP[(size_t)Bc * CH * DINNER * DSTATE];
__device__ float g_hP[(size_t)Bc * CH * DINNER * DSTATE];
__device__ float g_h0[(size_t)Bc * CH * DINNER * DSTATE];

// ---------------- helpers ----------------
__device__ __forceinline__ uint32_t smem_u32(const void* p) {
    uint32_t a;
    asm("{ .reg .u64 t; cvta.to.shared.u64 t, %1; cvt.u32.u64 %0, t; }" : "=r"(a) : "l"(p));
    return a;
}
#define CP16(dst, src) asm volatile("cp.async.cg.shared.global [%0], [%1], 16;" \
    :: "r"(dst), "l"(src) : "memory")
#define CP_COMMIT()    asm volatile("cp.async.commit_group;" ::: "memory")
#define CP_WAIT(n)     asm volatile("cp.async.wait_group %0;" :: "n"(n) : "memory")

__device__ __forceinline__ void store2(__half* C, size_t off, float v0, float v1) {
    *(__half2*)(C + off) = __floats2half2_rn(v0, v1);
}
__device__ __forceinline__ void store2(float* C, size_t off, float v0, float v1) {
    *(float2*)(C + off) = make_float2(v0, v1);
}
__device__ __forceinline__ void store1(__half* C, size_t off, float v0) { C[off] = __float2half(v0); }
__device__ __forceinline__ void store1(float* C, size_t off, float v0)  { C[off] = v0; }

// ---------------- fp16 1-term GEMM ----------------
// C[m,n] = f(sum_k A[m,k]*B[n,k] + bias), A/B fp16 K-major.  BMx128 tile, BK=64.
template<int BM, typename OutT>
__global__ __launch_bounds__(256, 2)
void gemm_h1(const __half* __restrict__ A,
             const __half* __restrict__ Bw,
             OutT* __restrict__ C, int ldc, int Nact, int Kh,
             const float* __restrict__ bias,
             const float* __restrict__ resid, int ldr, int act) {
    constexpr int ABYTES = BM * 128;
    constexpr int BBYTES = 128 * 128;
    constexpr int STG    = ABYTES + BBYTES;
    constexpr int WMC    = BM / 32;
    constexpr int WNC    = 8 / WMC;
    constexpr int WTN    = 128 / WNC;
    constexpr int BJ     = WTN / 8;

    extern __shared__ __align__(1024) unsigned char sm[];
    uint32_t sbase = smem_u32(sm);
    int tid = threadIdx.x, lane = tid & 31, wid = tid >> 5;
    int bm = blockIdx.y * BM, bn = blockIdx.x * 128;
    int wm = wid % WMC, wn = wid / WMC;
    size_t lda = (size_t)Kh;

    float acc[2][BJ][4];
    #pragma unroll
    for (int i = 0; i < 2; i++)
        #pragma unroll
        for (int j = 0; j < BJ; j++)
            #pragma unroll
            for (int q = 0; q < 4; q++) acc[i][j][q] = 0.f;

    const int nch = Kh >> 6;

    auto issue_load = [&](int stage, int c) {
        int off = c * 64;
        uint32_t sA = sbase + stage * STG;
        uint32_t sB = sA + ABYTES;
        #pragma unroll
        for (int it = 0; it < BM / 32; it++) {
            int idx = tid + it * 256;
            int r = idx >> 3, u = idx & 7;
            CP16(sA + r * 128 + ((u ^ (r & 7)) << 4),
                 __cvta_generic_to_global(A + (size_t)(bm + r) * lda + off + u * 8));
        }
        #pragma unroll
        for (int it = 0; it < 4; it++) {
            int idx = tid + it * 256;
            int r = idx >> 3, u = idx & 7;
            CP16(sB + r * 128 + ((u ^ (r & 7)) << 4),
                 __cvta_generic_to_global(Bw + (size_t)(bn + r) * lda + off + u * 8));
        }
        CP_COMMIT();
    };

    issue_load(0, 0);
    if (nch > 1) issue_load(1, 1);

    for (int c = 0; c < nch; c++) {
        int stage = c % 3;
        if (c + 2 < nch) { issue_load((c + 2) % 3, c + 2); CP_WAIT(2); }
        else if (c + 1 < nch) CP_WAIT(1);
        else CP_WAIT(0);
        __syncthreads();

        uint32_t sA = sbase + stage * STG;
        uint32_t sB = sA + ABYTES;
        #pragma unroll
        for (int ks = 0; ks < 4; ks++) {
            uint32_t a[2][4], b[BJ][2];
            #pragma unroll
            for (int i = 0; i < 2; i++) {
                int r = wm * 32 + i * 16 + (lane & 15);
                int u = ks * 2 + (lane >> 4);
                uint32_t addr = sA + r * 128 + ((u ^ (r & 7)) << 4);
                asm volatile("ldmatrix.sync.aligned.m8n8.x4.shared.b16 {%0,%1,%2,%3}, [%4];"
                    : "=r"(a[i][0]), "=r"(a[i][1]), "=r"(a[i][2]), "=r"(a[i][3]) : "r"(addr));
            }
            #pragma unroll
            for (int jj = 0; jj < BJ / 2; jj++) {
                int r = wn * WTN + jj * 16 + ((lane >> 4) << 3) + (lane & 7);
                int u = ks * 2 + ((lane >> 3) & 1);
                uint32_t addr = sB + r * 128 + ((u ^ (r & 7)) << 4);
                asm volatile("ldmatrix.sync.aligned.m8n8.x4.shared.b16 {%0,%1,%2,%3}, [%4];"
                    : "=r"(b[jj*2][0]), "=r"(b[jj*2][1]), "=r"(b[jj*2+1][0]), "=r"(b[jj*2+1][1])
                    : "r"(addr));
            }
            #pragma unroll
            for (int i = 0; i < 2; i++)
                #pragma unroll
                for (int j = 0; j < BJ; j++)
                    asm volatile(
                        "mma.sync.aligned.m16n8k16.row.col.f32.f16.f16.f32 "
                        "{%0,%1,%2,%3}, {%4,%5,%6,%7}, {%8,%9}, {%0,%1,%2,%3};"
                        : "+f"(acc[i][j][0]), "+f"(acc[i][j][1]),
                          "+f"(acc[i][j][2]), "+f"(acc[i][j][3])
                        : "r"(a[i][0]), "r"(a[i][1]), "r"(a[i][2]), "r"(a[i][3]),
                          "r"(b[j][0]), "r"(b[j][1]));
        }
        __syncthreads();
    }

    // ---- epilogue ----
    #pragma unroll
    for (int i = 0; i < 2; i++) {
        int r0 = bm + wm * 32 + i * 16 + (lane >> 2);
        #pragma unroll
        for (int j = 0; j < BJ; j++) {
            int n0 = bn + wn * WTN + j * 8 + 2 * (lane & 3);
            #pragma unroll
            for (int h = 0; h < 2; h++) {
                int r = r0 + h * 8;
                float v0 = acc[i][j][h * 2 + 0];
                float v1 = acc[i][j][h * 2 + 1];
                if (bias) { v0 += bias[n0]; v1 += bias[n0 + 1]; }
                if (act) {
                    v0 = (v0 > 20.f) ? v0 : log1pf(expf(v0));
                    v1 = (v1 > 20.f) ? v1 : log1pf(expf(v1));
                }
                if (resid) {
                    v0 += resid[(size_t)r * ldr + n0];
                    v1 += resid[(size_t)r * ldr + n0 + 1];
                }
                if (n0 + 1 < Nact)      store2(C, (size_t)r * ldc + n0, v0, v1);
                else if (n0 < Nact)     store1(C, (size_t)r * ldc + n0, v0);
            }
        }
    }
}

// ---------------- weight -> fp16 (row/col padding) ----------------
__global__ __launch_bounds__(256)
void wext1_kernel(const float* __restrict__ W, __half* __restrict__ out,
                  int Rin, int Kact, int Kp, int total) {
    int idx = blockIdx.x * 256 + threadIdx.x;
    if (idx >= total) return;
    int r = idx / Kp, k = idx - r * Kp;
    float v = (r < Rin && k < Kact) ? W[(size_t)r * Kact + k] : 0.f;
    out[idx] = __float2half(v);
}

// ---------------- LayerNorm -> fp16 ----------------
__global__ __launch_bounds__(256)
void ln_h(const float* __restrict__ x, const float* __restrict__ g,
          const float* __restrict__ b) {
    int row = blockIdx.x, tid = threadIdx.x;
    const float* xr = x + (size_t)row * DIMc;
    float sum = 0.f, sq = 0.f;
    for (int i = tid; i < DIMc; i += 256) {
        float v = xr[i];
        sum += v; sq += v * v;
    }
    #pragma unroll
    for (int o = 16; o; o >>= 1) {
        sum += __shfl_xor_sync(0xffffffffu, sum, o);
        sq  += __shfl_xor_sync(0xffffffffu, sq, o);
    }
    __shared__ float s1[8], s2[8], red[2];
    int w = tid >> 5, l = tid & 31;
    if (l == 0) { s1[w] = sum; s2[w] = sq; }
    __syncthreads();
    if (tid == 0) {
        float a = 0.f, c = 0.f;
        #pragma unroll
        for (int i = 0; i < 8; i++) { a += s1[i]; c += s2[i]; }
        float mu = a / DIMc;
        red[0] = mu;
        red[1] = c / DIMc - mu * mu;
    }
    __syncthreads();
    float mu = red[0];
    float inv = rsqrtf(red[1] + 1e-5f);
    __half* o = g_xnH + (size_t)row * DIMc;
    for (int i = tid; i < DIMc; i += 256)
        o[i] = __float2half((xr[i] - mu) * inv * g[i] + b[i]);
}

// ---------------- depthwise conv + SiLU -> fp16 uc ----------------
__global__ __launch_bounds__(256)
void conv_h(const float* __restrict__ convw, const float* __restrict__ convb) {
    int idx = blockIdx.x * 256 + threadIdx.x;
    if (idx >= MROWS * DINNER) return;
    int d = idx & (DINNER - 1);
    int m = idx >> 11;
    int l = m & (Lc - 1);
    float acc = convb[d];
    #pragma unroll
    for (int k = 0; k < DCONV; k++) {
        int ll = l - (DCONV - 1) + k;
        if (ll >= 0)
            acc = fmaf(__half2float(g_xzH[(size_t)(m - (DCONV - 1) + k) * 4096 + d]),
                       convw[d * DCONV + k], acc);
    }
    acc = acc / (1.f + expf(-acc));
    g_ucH[idx] = __float2half(acc);
}

// ---------------- dt_r slice -> fp16 (pad 64->128) ----------------
__global__ __launch_bounds__(256)
void dtr_h() {
    int idx = blockIdx.x * 256 + threadIdx.x;
    if (idx >= MROWS * 128) return;
    int m = idx >> 7, k = idx & 127;
    float v = (k < DTRANK) ? g_xdbl[(size_t)m * XDBL_N + k] : 0.f;
    g_dtrH[idx] = __float2half(v);
}

// ---------------- chunked scan: pass 1 (per-chunk transition) ----------------
__global__ __launch_bounds__(256)
void scan_p1(const float* __restrict__ A_log) {
    int t = blockIdx.x * 256 + threadIdx.x;    // (b, c, d, n)
    int n = t & 15;
    int d = (t >> 4) & (DINNER - 1);
    int c = (t >> 15) & (CH - 1);
    int b = t >> 18;
    float A = -expf(A_log[d * DSTATE + n]);
    float a = 1.f, h = 0.f;
    size_t base = (size_t)b * Lc + c * CL;
    for (int l = 0; l < CL; l++) {
        size_t m = base + l;
        float dt = __half2float(g_dtH[m * DINNER + d]);
        float u  = __half2float(g_ucH[m * DINNER + d]);
        float Bn = g_xdbl[m * XDBL_N + DTRANK + n];
        float dA = expf(dt * A);
        h = fmaf(dA, h, dt * u * Bn);
        a *= dA;
    }
    g_aP[t] = a;
    g_hP[t] = h;
}

// ---------------- chunked scan: pass 2 (chain carries) ----------------
__global__ __launch_bounds__(256)
void scan_p2() {
    int t = blockIdx.x * 256 + threadIdx.x;    // (b, d, n): 131072
    int n = t & 15;
    int dn = t & (DINNER * DSTATE - 1);
    int b = t >> 15;
    (void)n;
    float h0 = 0.f;
    #pragma unroll
    for (int c = 0; c < CH; c++) {
        size_t idx = ((size_t)(b * CH + c) << 15) + dn;
        g_h0[idx] = h0;
        h0 = fmaf(g_aP[idx], h0, g_hP[idx]);
    }
}

// ---------------- chunked scan: pass 3 (emit y) ----------------
__global__ __launch_bounds__(256)
void scan_p3(const float* __restrict__ A_log, const float* __restrict__ Dp) {
    int t = blockIdx.x * 256 + threadIdx.x;
    int n = t & 15;
    int d = (t >> 4) & (DINNER - 1);
    int c = (t >> 15) & (CH - 1);
    int b = t >> 18;
    float A  = -expf(A_log[d * DSTATE + n]);
    float Dd = Dp[d];
    float h  = g_h0[t];
    size_t base = (size_t)b * Lc + c * CL;
    for (int l = 0; l < CL; l++) {
        size_t m = base + l;
        float dt = __half2float(g_dtH[m * DINNER + d]);
        float u  = __half2float(g_ucH[m * DINNER + d]);
        float Bn = g_xdbl[m * XDBL_N + DTRANK + n];
        float Cn = g_xdbl[m * XDBL_N + DTRANK + DSTATE + n];
        float dA = expf(dt * A);
        h = fmaf(dA, h, dt * u * Bn);
        float p = h * Cn;
        p += __shfl_xor_sync(0xffffffffu, p, 8);
        p += __shfl_xor_sync(0xffffffffu, p, 4);
        p += __shfl_xor_sync(0xffffffffu, p, 2);
        p += __shfl_xor_sync(0xffffffffu, p, 1);
        if (n == 0) {
            float z = __half2float(g_xzH[m * 4096 + DINNER + d]);
            float y = (p + u * Dd) * (z / (1.f + expf(-z)));
            g_yH[m * DINNER + d] = __float2half(y);
        }
    }
}

// ---------------- launch ----------------
extern "C" void kernel_launch(void* const* d_in, const int* in_sizes, int n_in,
                              void* d_out, int out_size) {
    const float* x      = (const float*)d_in[0];
    const float* ln_g   = (const float*)d_in[1];
    const float* ln_b   = (const float*)d_in[2];
    const float* W_in   = (const float*)d_in[3];
    const float* conv_w = (const float*)d_in[4];
    const float* conv_b = (const float*)d_in[5];
    const float* W_x    = (const float*)d_in[6];
    const float* W_dt   = (const float*)d_in[7];
    const float* b_dt   = (const float*)d_in[8];
    const float* A_log  = (const float*)d_in[9];
    const float* Dvec   = (const float*)d_in[10];
    const float* W_out  = (const float*)d_in[11];
    float* out = (float*)d_out;

    __half *xnH, *WinH, *xzH, *ucH, *WxH, *dtrH, *WdtH, *dtH, *yH, *WoutH;
    float *xdbl;
    cudaGetSymbolAddress((void**)&xnH,   g_xnH);
    cudaGetSymbolAddress((void**)&WinH,  g_WinH);
    cudaGetSymbolAddress((void**)&xzH,   g_xzH);
    cudaGetSymbolAddress((void**)&ucH,   g_ucH);
    cudaGetSymbolAddress((void**)&WxH,   g_WxH);
    cudaGetSymbolAddress((void**)&xdbl,  g_xdbl);
    cudaGetSymbolAddress((void**)&dtrH,  g_dtrH);
    cudaGetSymbolAddress((void**)&WdtH,  g_WdtH);
    cudaGetSymbolAddress((void**)&dtH,   g_dtH);
    cudaGetSymbolAddress((void**)&yH,    g_yH);
    cudaGetSymbolAddress((void**)&WoutH, g_WoutH);

    static int smem_set = 0;
    if (!smem_set) {
        cudaFuncSetAttribute((const void*)gemm_h1<128, __half>, cudaFuncAttributeMaxDynamicSharedMemorySize, 98304);
        cudaFuncSetAttribute((const void*)gemm_h1<128, float>,  cudaFuncAttributeMaxDynamicSharedMemorySize, 98304);
        cudaFuncSetAttribute((const void*)gemm_h1<64, float>,   cudaFuncAttributeMaxDynamicSharedMemorySize, 73728);
        smem_set = 1;
    }
    const int SM128 = 98304;
    const int SM64  = 73728;

    // weight conversions (fp16)
    wext1_kernel<<<(4096 * 1024 + 255) / 256, 256>>>(W_in,  WinH,  4096,   DIMc,   DIMc,   4096 * 1024);
    wext1_kernel<<<(128 * 2048 + 255) / 256, 256>>>(W_x,   WxH,   XDBL_N, DINNER, DINNER, 128 * 2048);
    wext1_kernel<<<(2048 * 128 + 255) / 256, 256>>>(W_dt,  WdtH,  DINNER, DTRANK, 128,    2048 * 128);
    wext1_kernel<<<(1024 * 2048 + 255) / 256, 256>>>(W_out, WoutH, DIMc,   DINNER, DINNER, 1024 * 2048);

    // LN -> fp16
    ln_h<<<MROWS, 256>>>(x, ln_g, ln_b);

    // GEMM1: xz = xn @ W_in^T   (8192 x 4096, K=1024) -> fp16
    gemm_h1<128, __half><<<dim3(4096 / 128, MROWS / 128), 256, SM128>>>(
        xnH, WinH, xzH, 4096, 4096, DIMc, nullptr, nullptr, 0, 0);

    // conv + SiLU -> fp16 uc
    conv_h<<<(MROWS * DINNER) / 256, 256>>>(conv_w, conv_b);

    // GEMM2: x_dbl = uc @ W_x^T  (8192 x 96 pad 128, K=2048) -> fp32
    gemm_h1<64, float><<<dim3(1, MROWS / 64), 256, SM64>>>(
        ucH, WxH, xdbl, XDBL_N, XDBL_N, DINNER, nullptr, nullptr, 0, 0);

    // dt_r -> fp16
    dtr_h<<<(MROWS * 128) / 256, 256>>>();

    // GEMM3: dt = softplus(dt_r @ W_dt^T + b_dt)  (8192 x 2048, K=128) -> fp16
    gemm_h1<128, __half><<<dim3(DINNER / 128, MROWS / 128), 256, SM128>>>(
        dtrH, WdtH, dtH, DINNER, DINNER, 128, b_dt, nullptr, 0, 1);

    // chunked scan
    scan_p1<<<(Bc * CH * DINNER * DSTATE) / 256, 256>>>(A_log);
    scan_p2<<<(Bc * DINNER * DSTATE) / 256, 256>>>();
    scan_p3<<<(Bc * CH * DINNER * DSTATE) / 256, 256>>>(A_log, Dvec);

    // GEMM4: out = x + y @ W_out^T  (8192 x 1024, K=2048) -> fp32 + resid
    gemm_h1<128, float><<<dim3(DIMc / 128, MROWS / 128), 256, SM128>>>(
        yH, WoutH, out, DIMc, DIMc, DINNER, nullptr, x, DIMc, 0);
}

// round 11
// speedup vs baseline: 2.7882x; 1.0455x over previous
#include <cuda_runtime.h>
#include <cuda_fp16.h>
#include <math.h>
#include <stdint.h>

// ---------------- problem constants ----------------
#define Bc      4
#define Lc      2048
#define DIMc    1024
#define DINNER  2048
#define DSTATE  16
#define DCONV   4
#define DTRANK  64
#define MROWS   (Bc*Lc)        // 8192
#define XDBL_N  96
#define CH      16             // scan chunks
#define CL      (Lc/CH)        // 128 tokens per chunk
#define KSPLIT  4              // GEMM2 K-split

// ---------------- scratch (device globals) ----------------
__device__ __align__(128) __half g_xnH  [(size_t)MROWS * 1024];
__device__ __align__(128) __half g_WinH [(size_t)4096 * 1024];
__device__ __align__(128) __half g_xzH  [(size_t)MROWS * 4096];   // u|z fp16
__device__ __align__(128) __half g_ucH  [(size_t)MROWS * 2048];
__device__ __align__(128) __half g_WxH  [(size_t)128 * 2048];
__device__ float                 g_xdblP[(size_t)KSPLIT * MROWS * XDBL_N]; // K-split partials
__device__ float                 g_xdbl [(size_t)MROWS * XDBL_N]; // B,C,dt_r fp32
__device__ __align__(128) __half g_dtrH [(size_t)MROWS * 128];    // pad cols stay 0
__device__ __align__(128) __half g_WdtH [(size_t)2048 * 128];
__device__ __align__(128) __half g_dtH  [(size_t)MROWS * 2048];
__device__ __align__(128) __half g_yH   [(size_t)MROWS * 2048];
__device__ __align__(128) __half g_WoutH[(size_t)1024 * 2048];
// chunked-scan state: [Bc][CH][DINNER][DSTATE]
__device__ float g_aP[(size_t)Bc * CH * DINNER * DSTATE];
__device__ float g_hP[(size_t)Bc * CH * DINNER * DSTATE];
__device__ float g_h0[(size_t)Bc * CH * DINNER * DSTATE];

// ---------------- helpers ----------------
__device__ __forceinline__ uint32_t smem_u32(const void* p) {
    uint32_t a;
    asm("{ .reg .u64 t; cvta.to.shared.u64 t, %1; cvt.u32.u64 %0, t; }" : "=r"(a) : "l"(p));
    return a;
}
#define CP16(dst, src) asm volatile("cp.async.cg.shared.global [%0], [%1], 16;" \
    :: "r"(dst), "l"(src) : "memory")
#define CP_COMMIT()    asm volatile("cp.async.commit_group;" ::: "memory")
#define CP_WAIT(n)     asm volatile("cp.async.wait_group %0;" :: "n"(n) : "memory")

__device__ __forceinline__ void store2(__half* C, size_t off, float v0, float v1) {
    *(__half2*)(C + off) = __floats2half2_rn(v0, v1);
}
__device__ __forceinline__ void store2(float* C, size_t off, float v0, float v1) {
    *(float2*)(C + off) = make_float2(v0, v1);
}
__device__ __forceinline__ void store1(__half* C, size_t off, float v0) { C[off] = __float2half(v0); }
__device__ __forceinline__ void store1(float* C, size_t off, float v0)  { C[off] = v0; }

// ---------------- fp16 1-term GEMM ----------------
// C[m,n] = f(sum_k A[m,k]*B[n,k] + bias), fp16 K-major, row stride ldab.
// When gridDim.z > 1: K-split — slice z handles K range [z*Kh, (z+1)*Kh),
// output slab z of C (slab pitch MROWS*ldc).
template<int BM, typename OutT>
__global__ __launch_bounds__(256, 2)
void gemm_h1(const __half* __restrict__ A,
             const __half* __restrict__ Bw,
             OutT* __restrict__ C, int ldc, int Nact, int Kh, int ldab,
             const float* __restrict__ bias,
             const float* __restrict__ resid, int ldr, int act) {
    constexpr int ABYTES = BM * 128;
    constexpr int BBYTES = 128 * 128;
    constexpr int STG    = ABYTES + BBYTES;
    constexpr int WMC    = BM / 32;
    constexpr int WNC    = 8 / WMC;
    constexpr int WTN    = 128 / WNC;
    constexpr int BJ     = WTN / 8;

    extern __shared__ __align__(1024) unsigned char sm[];
    uint32_t sbase = smem_u32(sm);
    int tid = threadIdx.x, lane = tid & 31, wid = tid >> 5;
    int bm = blockIdx.y * BM, bn = blockIdx.x * 128;
    int wm = wid % WMC, wn = wid / WMC;
    size_t lda = (size_t)ldab;

    // K-split offsets
    A  += (size_t)blockIdx.z * Kh;
    Bw += (size_t)blockIdx.z * Kh;
    C  += (size_t)blockIdx.z * (size_t)MROWS * ldc;

    float acc[2][BJ][4];
    #pragma unroll
    for (int i = 0; i < 2; i++)
        #pragma unroll
        for (int j = 0; j < BJ; j++)
            #pragma unroll
            for (int q = 0; q < 4; q++) acc[i][j][q] = 0.f;

    const int nch = Kh >> 6;

    auto issue_load = [&](int stage, int c) {
        int off = c * 64;
        uint32_t sA = sbase + stage * STG;
        uint32_t sB = sA + ABYTES;
        #pragma unroll
        for (int it = 0; it < BM / 32; it++) {
            int idx = tid + it * 256;
            int r = idx >> 3, u = idx & 7;
            CP16(sA + r * 128 + ((u ^ (r & 7)) << 4),
                 __cvta_generic_to_global(A + (size_t)(bm + r) * lda + off + u * 8));
        }
        #pragma unroll
        for (int it = 0; it < 4; it++) {
            int idx = tid + it * 256;
            int r = idx >> 3, u = idx & 7;
            CP16(sB + r * 128 + ((u ^ (r & 7)) << 4),
                 __cvta_generic_to_global(Bw + (size_t)(bn + r) * lda + off + u * 8));
        }
        CP_COMMIT();
    };

    issue_load(0, 0);
    if (nch > 1) issue_load(1, 1);

    for (int c = 0; c < nch; c++) {
        int stage = c % 3;
        if (c + 2 < nch) { issue_load((c + 2) % 3, c + 2); CP_WAIT(2); }
        else if (c + 1 < nch) CP_WAIT(1);
        else CP_WAIT(0);
        __syncthreads();

        uint32_t sA = sbase + stage * STG;
        uint32_t sB = sA + ABYTES;
        #pragma unroll
        for (int ks = 0; ks < 4; ks++) {
            uint32_t a[2][4], b[BJ][2];
            #pragma unroll
            for (int i = 0; i < 2; i++) {
                int r = wm * 32 + i * 16 + (lane & 15);
                int u = ks * 2 + (lane >> 4);
                uint32_t addr = sA + r * 128 + ((u ^ (r & 7)) << 4);
                asm volatile("ldmatrix.sync.aligned.m8n8.x4.shared.b16 {%0,%1,%2,%3}, [%4];"
                    : "=r"(a[i][0]), "=r"(a[i][1]), "=r"(a[i][2]), "=r"(a[i][3]) : "r"(addr));
            }
            #pragma unroll
            for (int jj = 0; jj < BJ / 2; jj++) {
                int r = wn * WTN + jj * 16 + ((lane >> 4) << 3) + (lane & 7);
                int u = ks * 2 + ((lane >> 3) & 1);
                uint32_t addr = sB + r * 128 + ((u ^ (r & 7)) << 4);
                asm volatile("ldmatrix.sync.aligned.m8n8.x4.shared.b16 {%0,%1,%2,%3}, [%4];"
                    : "=r"(b[jj*2][0]), "=r"(b[jj*2][1]), "=r"(b[jj*2+1][0]), "=r"(b[jj*2+1][1])
                    : "r"(addr));
            }
            #pragma unroll
            for (int i = 0; i < 2; i++)
                #pragma unroll
                for (int j = 0; j < BJ; j++)
                    asm volatile(
                        "mma.sync.aligned.m16n8k16.row.col.f32.f16.f16.f32 "
                        "{%0,%1,%2,%3}, {%4,%5,%6,%7}, {%8,%9}, {%0,%1,%2,%3};"
                        : "+f"(acc[i][j][0]), "+f"(acc[i][j][1]),
                          "+f"(acc[i][j][2]), "+f"(acc[i][j][3])
                        : "r"(a[i][0]), "r"(a[i][1]), "r"(a[i][2]), "r"(a[i][3]),
                          "r"(b[j][0]), "r"(b[j][1]));
        }
        __syncthreads();
    }

    // ---- epilogue ----
    #pragma unroll
    for (int i = 0; i < 2; i++) {
        int r0 = bm + wm * 32 + i * 16 + (lane >> 2);
        #pragma unroll
        for (int j = 0; j < BJ; j++) {
            int n0 = bn + wn * WTN + j * 8 + 2 * (lane & 3);
            #pragma unroll
            for (int h = 0; h < 2; h++) {
                int r = r0 + h * 8;
                float v0 = acc[i][j][h * 2 + 0];
                float v1 = acc[i][j][h * 2 + 1];
                if (bias) { v0 += bias[n0]; v1 += bias[n0 + 1]; }
                if (act) {
                    v0 = (v0 > 20.f) ? v0 : log1pf(expf(v0));
                    v1 = (v1 > 20.f) ? v1 : log1pf(expf(v1));
                }
                if (resid) {
                    v0 += resid[(size_t)r * ldr + n0];
                    v1 += resid[(size_t)r * ldr + n0 + 1];
                }
                if (n0 + 1 < Nact)      store2(C, (size_t)r * ldc + n0, v0, v1);
                else if (n0 < Nact)     store1(C, (size_t)r * ldc + n0, v0);
            }
        }
    }
}

// ---------------- weight -> fp16 (row/col padding) ----------------
__global__ __launch_bounds__(256)
void wext1_kernel(const float* __restrict__ W, __half* __restrict__ out,
                  int Rin, int Kact, int Kp, int total) {
    int idx = blockIdx.x * 256 + threadIdx.x;
    if (idx >= total) return;
    int r = idx / Kp, k = idx - r * Kp;
    float v = (r < Rin && k < Kact) ? W[(size_t)r * Kact + k] : 0.f;
    out[idx] = __float2half(v);
}

// ---------------- LayerNorm -> fp16 ----------------
__global__ __launch_bounds__(256)
void ln_h(const float* __restrict__ x, const float* __restrict__ g,
          const float* __restrict__ b) {
    int row = blockIdx.x, tid = threadIdx.x;
    const float* xr = x + (size_t)row * DIMc;
    float sum = 0.f, sq = 0.f;
    for (int i = tid; i < DIMc; i += 256) {
        float v = xr[i];
        sum += v; sq += v * v;
    }
    #pragma unroll
    for (int o = 16; o; o >>= 1) {
        sum += __shfl_xor_sync(0xffffffffu, sum, o);
        sq  += __shfl_xor_sync(0xffffffffu, sq, o);
    }
    __shared__ float s1[8], s2[8], red[2];
    int w = tid >> 5, l = tid & 31;
    if (l == 0) { s1[w] = sum; s2[w] = sq; }
    __syncthreads();
    if (tid == 0) {
        float a = 0.f, c = 0.f;
        #pragma unroll
        for (int i = 0; i < 8; i++) { a += s1[i]; c += s2[i]; }
        float mu = a / DIMc;
        red[0] = mu;
        red[1] = c / DIMc - mu * mu;
    }
    __syncthreads();
    float mu = red[0];
    float inv = rsqrtf(red[1] + 1e-5f);
    __half* o = g_xnH + (size_t)row * DIMc;
    for (int i = tid; i < DIMc; i += 256)
        o[i] = __float2half((xr[i] - mu) * inv * g[i] + b[i]);
}

// ---------------- depthwise conv + SiLU -> fp16 uc ----------------
__global__ __launch_bounds__(256)
void conv_h(const float* __restrict__ convw, const float* __restrict__ convb) {
    int idx = blockIdx.x * 256 + threadIdx.x;
    if (idx >= MROWS * DINNER) return;
    int d = idx & (DINNER - 1);
    int m = idx >> 11;
    int l = m & (Lc - 1);
    float acc = convb[d];
    #pragma unroll
    for (int k = 0; k < DCONV; k++) {
        int ll = l - (DCONV - 1) + k;
        if (ll >= 0)
            acc = fmaf(__half2float(g_xzH[(size_t)(m - (DCONV - 1) + k) * 4096 + d]),
                       convw[d * DCONV + k], acc);
    }
    acc = acc / (1.f + expf(-acc));
    g_ucH[idx] = __float2half(acc);
}

// ---------------- reduce K-split partials -> xdbl fp32 + dtr fp16 ----------------
__global__ __launch_bounds__(256)
void reduce_xdbl() {
    int idx = blockIdx.x * 256 + threadIdx.x;    // over MROWS*XDBL_N
    if (idx >= MROWS * XDBL_N) return;
    float v = 0.f;
    #pragma unroll
    for (int s = 0; s < KSPLIT; s++)
        v += g_xdblP[(size_t)s * MROWS * XDBL_N + idx];
    g_xdbl[idx] = v;
    int m = idx / XDBL_N, k = idx - m * XDBL_N;
    if (k < DTRANK)
        g_dtrH[(size_t)m * 128 + k] = __float2half(v);   // pad cols stay zero-init
}

// ---------------- chunked scan: pass 1 (per-chunk transition) ----------------
__global__ __launch_bounds__(256)
void scan_p1(const float* __restrict__ A_log) {
    int t = blockIdx.x * 256 + threadIdx.x;    // (b, c, d, n)
    int n = t & 15;
    int d = (t >> 4) & (DINNER - 1);
    int c = (t >> 15) & (CH - 1);
    int b = t >> 19;
    float A = -expf(A_log[d * DSTATE + n]);
    float a = 1.f, h = 0.f;
    size_t base = (size_t)b * Lc + c * CL;
    for (int l = 0; l < CL; l++) {
        size_t m = base + l;
        float dt = __half2float(g_dtH[m * DINNER + d]);
        float u  = __half2float(g_ucH[m * DINNER + d]);
        float Bn = g_xdbl[m * XDBL_N + DTRANK + n];
        float dA = expf(dt * A);
        h = fmaf(dA, h, dt * u * Bn);
        a *= dA;
    }
    g_aP[t] = a;
    g_hP[t] = h;
}

// ---------------- chunked scan: pass 2 (chain carries) ----------------
__global__ __launch_bounds__(256)
void scan_p2() {
    int t = blockIdx.x * 256 + threadIdx.x;    // (b, d, n): 131072
    int dn = t & (DINNER * DSTATE - 1);
    int b = t >> 15;
    float h0 = 0.f;
    #pragma unroll
    for (int c = 0; c < CH; c++) {
        size_t idx = ((size_t)(b * CH + c) << 15) + dn;
        g_h0[idx] = h0;
        h0 = fmaf(g_aP[idx], h0, g_hP[idx]);
    }
}

// ---------------- chunked scan: pass 3 (emit y) ----------------
__global__ __launch_bounds__(256)
void scan_p3(const float* __restrict__ A_log, const float* __restrict__ Dp) {
    int t = blockIdx.x * 256 + threadIdx.x;
    int n = t & 15;
    int d = (t >> 4) & (DINNER - 1);
    int c = (t >> 15) & (CH - 1);
    int b = t >> 19;
    float A  = -expf(A_log[d * DSTATE + n]);
    float Dd = Dp[d];
    float h  = g_h0[t];
    size_t base = (size_t)b * Lc + c * CL;
    for (int l = 0; l < CL; l++) {
        size_t m = base + l;
        float dt = __half2float(g_dtH[m * DINNER + d]);
        float u  = __half2float(g_ucH[m * DINNER + d]);
        float Bn = g_xdbl[m * XDBL_N + DTRANK + n];
        float Cn = g_xdbl[m * XDBL_N + DTRANK + DSTATE + n];
        float dA = expf(dt * A);
        h = fmaf(dA, h, dt * u * Bn);
        float p = h * Cn;
        p += __shfl_xor_sync(0xffffffffu, p, 8);
        p += __shfl_xor_sync(0xffffffffu, p, 4);
        p += __shfl_xor_sync(0xffffffffu, p, 2);
        p += __shfl_xor_sync(0xffffffffu, p, 1);
        if (n == 0) {
            float z = __half2float(g_xzH[m * 4096 + DINNER + d]);
            float y = (p + u * Dd) * (z / (1.f + expf(-z)));
            g_yH[m * DINNER + d] = __float2half(y);
        }
    }
}

// ---------------- launch ----------------
extern "C" void kernel_launch(void* const* d_in, const int* in_sizes, int n_in,
                              void* d_out, int out_size) {
    const float* x      = (const float*)d_in[0];
    const float* ln_g   = (const float*)d_in[1];
    const float* ln_b   = (const float*)d_in[2];
    const float* W_in   = (const float*)d_in[3];
    const float* conv_w = (const float*)d_in[4];
    const float* conv_b = (const float*)d_in[5];
    const float* W_x    = (const float*)d_in[6];
    const float* W_dt   = (const float*)d_in[7];
    const float* b_dt   = (const float*)d_in[8];
    const float* A_log  = (const float*)d_in[9];
    const float* Dvec   = (const float*)d_in[10];
    const float* W_out  = (const float*)d_in[11];
    float* out = (float*)d_out;

    __half *xnH, *WinH, *xzH, *ucH, *WxH, *dtrH, *WdtH, *dtH, *yH, *WoutH;
    float *xdbl, *xdblP;
    cudaGetSymbolAddress((void**)&xnH,   g_xnH);
    cudaGetSymbolAddress((void**)&WinH,  g_WinH);
    cudaGetSymbolAddress((void**)&xzH,   g_xzH);
    cudaGetSymbolAddress((void**)&ucH,   g_ucH);
    cudaGetSymbolAddress((void**)&WxH,   g_WxH);
    cudaGetSymbolAddress((void**)&xdbl,  g_xdbl);
    cudaGetSymbolAddress((void**)&xdblP, g_xdblP);
    cudaGetSymbolAddress((void**)&dtrH,  g_dtrH);
    cudaGetSymbolAddress((void**)&WdtH,  g_WdtH);
    cudaGetSymbolAddress((void**)&dtH,   g_dtH);
    cudaGetSymbolAddress((void**)&yH,    g_yH);
    cudaGetSymbolAddress((void**)&WoutH, g_WoutH);

    static int smem_set = 0;
    if (!smem_set) {
        cudaFuncSetAttribute((const void*)gemm_h1<128, __half>, cudaFuncAttributeMaxDynamicSharedMemorySize, 98304);
        cudaFuncSetAttribute((const void*)gemm_h1<128, float>,  cudaFuncAttributeMaxDynamicSharedMemorySize, 98304);
        cudaFuncSetAttribute((const void*)gemm_h1<64, float>,   cudaFuncAttributeMaxDynamicSharedMemorySize, 73728);
        smem_set = 1;
    }
    const int SM128 = 98304;
    const int SM64  = 73728;

    // #1, #2: weight conversions needed by GEMM1/GEMM4
    wext1_kernel<<<(4096 * 1024 + 255) / 256, 256>>>(W_in,  WinH,  4096, DIMc,   DIMc,   4096 * 1024);
    wext1_kernel<<<(1024 * 2048 + 255) / 256, 256>>>(W_out, WoutH, DIMc, DINNER, DINNER, 1024 * 2048);

    // #3: LN -> fp16
    ln_h<<<MROWS, 256>>>(x, ln_g, ln_b);

    // #4 (profiled): GEMM1: xz = xn @ W_in^T   (8192 x 4096, K=1024) -> fp16
    gemm_h1<128, __half><<<dim3(4096 / 128, MROWS / 128), 256, SM128>>>(
        xnH, WinH, xzH, 4096, 4096, DIMc, DIMc, nullptr, nullptr, 0, 0);

    // #5, #6: remaining weight conversions
    wext1_kernel<<<(128 * 2048 + 255) / 256, 256>>>(W_x,  WxH,  XDBL_N, DINNER, DINNER, 128 * 2048);
    wext1_kernel<<<(2048 * 128 + 255) / 256, 256>>>(W_dt, WdtH, DINNER, DTRANK, 128,    2048 * 128);

    // #7: conv + SiLU -> fp16 uc
    conv_h<<<(MROWS * DINNER) / 256, 256>>>(conv_w, conv_b);

    // #8: GEMM2 split-K: x_dbl partials (8192 x 96 pad 128, K=4x512)
    gemm_h1<64, float><<<dim3(1, MROWS / 64, KSPLIT), 256, SM64>>>(
        ucH, WxH, xdblP, XDBL_N, XDBL_N, DINNER / KSPLIT, DINNER, nullptr, nullptr, 0, 0);

    // #9: reduce partials -> xdbl fp32 + dtr fp16
    reduce_xdbl<<<(MROWS * XDBL_N + 255) / 256, 256>>>();

    // #10: GEMM3: dt = softplus(dt_r @ W_dt^T + b_dt)  (8192 x 2048, K=128) -> fp16
    gemm_h1<128, __half><<<dim3(DINNER / 128, MROWS / 128), 256, SM128>>>(
        dtrH, WdtH, dtH, DINNER, DINNER, 128, 128, b_dt, nullptr, 0, 1);

    // #11-13: chunked scan
    scan_p1<<<(Bc * CH * DINNER * DSTATE) / 256, 256>>>(A_log);
    scan_p2<<<(Bc * DINNER * DSTATE) / 256, 256>>>();
    scan_p3<<<(Bc * CH * DINNER * DSTATE) / 256, 256>>>(A_log, Dvec);

    // #14: GEMM4: out = x + y @ W_out^T  (8192 x 1024, K=2048) -> fp32 + resid
    gemm_h1<128, float><<<dim3(DIMc / 128, MROWS / 128), 256, SM128>>>(
        yH, WoutH, out, DIMc, DIMc, DINNER, DINNER, nullptr, x, DIMc, 0);
}